// round 14
// baseline (speedup 1.0000x reference)
#include <cuda_runtime.h>
#include <cstdint>
#include <cstddef>

#define NN    50000
#define DEG   16
#define FE    16
#define DH    128
#define DC    144
#define NL    3
#define NG    64
#define DOUT  10
#define BN_SCALE 0.9999950000374997f

#define BM    64
#define NT    ((NN + BM - 1) / BM)      // 782 tiles (NT*BM = 50048)
#define NPAD  (NT * BM)                 // 50048
#define GRID_F 152                      // persistent CTAs (1/SM)
#define NTHR  512
#define POOLN ((NL + 1) * NG * DH)

#define AS 148      // A row stride (floats); af banks (20g+t) conflict-free
#define HS 132      // h1 row stride; af banks (4g+t) conflict-free

// ---- fused-kernel smem (float indices) ----
#define F_AL1 0
#define F_BE1 128
#define F_AL2 256
#define F_BE2 384
#define F_BT  512                        // 64 ints
#define F_W1  640
#define F_W2  (F_W1 + DC * DH)           // 19072
#define F_A   (F_W2 + DH * DH)           // 35456
#define F_H1  (F_A + BM * AS)            // 44928
#define F_TOT (F_H1 + BM * HS)           // 53376 floats = 213504 B
#define SMEM_F (F_TOT * 4)

// ---- device scratch ----
__device__ uint32_t g_A[(size_t)NPAD * AS];   // gathered features (tf32 bits)
__device__ float g_hb0[(size_t)NN * DH];
__device__ float g_hb1[(size_t)NN * DH];
__device__ float g_edge_rep[(size_t)NN * FE];
__device__ float g_pool[POOLN];

// ---------------- helpers ----------------
__device__ __forceinline__ uint32_t tf32r(float x) {
    uint32_t r; asm("cvt.rna.tf32.f32 %0, %1;" : "=r"(r) : "f"(x)); return r;
}
__device__ __forceinline__ void mma_tf32(float* d,
                                         uint32_t a0, uint32_t a1, uint32_t a2, uint32_t a3,
                                         uint32_t b0, uint32_t b1) {
    asm volatile(
        "mma.sync.aligned.m16n8k8.row.col.f32.tf32.tf32.f32 "
        "{%0,%1,%2,%3}, {%4,%5,%6,%7}, {%8,%9}, {%0,%1,%2,%3};"
        : "+f"(d[0]), "+f"(d[1]), "+f"(d[2]), "+f"(d[3])
        : "r"(a0), "r"(a1), "r"(a2), "r"(a3), "r"(b0), "r"(b1));
}
__device__ __forceinline__ void cp_async16(uint32_t saddr, const void* gaddr) {
    asm volatile("cp.async.cg.shared.global [%0], [%1], 16;" :: "r"(saddr), "l"(gaddr));
}
#define CP_COMMIT() asm volatile("cp.async.commit_group;" ::: "memory")
#define CP_WAIT0()  asm volatile("cp.async.wait_group 0;" ::: "memory")

// ---------------- small kernels ----------------
__global__ void k_zero(float* __restrict__ p, int n) {
    int i = blockIdx.x * blockDim.x + threadIdx.x;
    if (i < n) p[i] = 0.f;
}
// edge_rep: 4 threads/node, each sums one 4-feat group over 16 edges (LDG.128).
__global__ void k_edge_rep(const float* __restrict__ ea, float* __restrict__ er) {
    int t4 = blockIdx.x * blockDim.x + threadIdx.x;
    if (t4 >= NN * 4) return;
    int i = t4 >> 2, q = t4 & 3;
    const float4* base = (const float4*)(ea + ((size_t)i * DEG) * FE) + q;
    float4 s = make_float4(1.f, 1.f, 1.f, 1.f);
#pragma unroll
    for (int k = 0; k < DEG; k++) {
        float4 v = __ldg(base + k * 4);
        s.x += v.x; s.y += v.y; s.z += v.z; s.w += v.w;
    }
    ((float4*)(er + (size_t)i * FE))[q] = s;
}
__global__ void __launch_bounds__(128) k_pool_rep(
    const float* __restrict__ h, const int* __restrict__ batch,
    float* __restrict__ pool) {
    __shared__ int sb[BM];
    int m0 = blockIdx.x * BM;
    if (threadIdx.x < BM)
        sb[threadIdx.x] = (m0 + threadIdx.x < NN) ? __ldg(&batch[m0 + threadIdx.x]) : -1;
    __syncthreads();
    int c = threadIdx.x;
    float s = 0.f; int curg = sb[0];
#pragma unroll
    for (int r0 = 0; r0 < BM; r0 += 8) {
        float v[8];
#pragma unroll
        for (int j = 0; j < 8; j++) {
            int node = m0 + r0 + j;
            v[j] = (node < NN) ? __ldg(&h[(size_t)node * DH + c]) : 0.f;
        }
#pragma unroll
        for (int j = 0; j < 8; j++) {
            int g = sb[r0 + j];
            if (g != curg) {
                if (curg >= 0) atomicAdd(&pool[curg * DH + c], s);
                s = 0.f; curg = g;
            }
            s += v[j];
        }
    }
    if (curg >= 0) atomicAdd(&pool[curg * DH + c], s);
}
__global__ void k_final(const float* __restrict__ pool, const float* __restrict__ Wp,
                        const float* __restrict__ bp, float* __restrict__ out) {
    int t = threadIdx.x;
    if (t >= NG * DOUT) return;
    int g = t / DOUT, o = t % DOUT;
    float s = 0.f;
#pragma unroll
    for (int l = 0; l < NL + 1; l++) s += __ldg(&bp[l * DOUT + o]);
#pragma unroll
    for (int l = 0; l < NL + 1; l++) {
        const float* P = pool + l * NG * DH + g * DH;
        const float* W = Wp + l * DH * DOUT;
        for (int k = 0; k < DH; k++) s += P[k] * __ldg(&W[k * DOUT + o]);
    }
    out[t] = s;
}

// ---------------------------------------------------------------------------
// Gather: warp per node, lane owns 4 cols -> coalesced LDG.128 per neighbor row.
__global__ void __launch_bounds__(256) k_gather(
    const float* __restrict__ hin, const int* __restrict__ edge_dst,
    const float* __restrict__ eps, int l,
    const float* __restrict__ er, uint32_t* __restrict__ A) {
    int w = (blockIdx.x * 256 + threadIdx.x) >> 5;
    int lane = threadIdx.x & 31;
    float epsv = __ldg(&eps[l]);
    float e1 = 1.f + epsv;

    int dv = __ldg(edge_dst + (size_t)w * DEG + (lane & 15));
    float4 own = __ldg((const float4*)(hin + (size_t)w * DH) + lane);
    float4 acc0, acc1;
    acc0.x = own.x * e1; acc0.y = own.y * e1; acc0.z = own.z * e1; acc0.w = own.w * e1;
    acc1 = make_float4(0.f, 0.f, 0.f, 0.f);
#pragma unroll
    for (int k = 0; k < DEG; k += 2) {
        int d0 = __shfl_sync(0xffffffffu, dv, k);
        int d1 = __shfl_sync(0xffffffffu, dv, k + 1);
        float4 v0 = __ldg((const float4*)(hin + (size_t)d0 * DH) + lane);
        float4 v1 = __ldg((const float4*)(hin + (size_t)d1 * DH) + lane);
        acc0.x += v0.x; acc0.y += v0.y; acc0.z += v0.z; acc0.w += v0.w;
        acc1.x += v1.x; acc1.y += v1.y; acc1.z += v1.z; acc1.w += v1.w;
    }
    float4 a;
    a.x = acc0.x + acc1.x; a.y = acc0.y + acc1.y;
    a.z = acc0.z + acc1.z; a.w = acc0.w + acc1.w;
    *(uint4*)(A + (size_t)w * AS + lane * 4) =
        make_uint4(tf32r(a.x), tf32r(a.y), tf32r(a.z), tf32r(a.w));
    if (lane < 4) {
        float4 v = __ldg((const float4*)(er + (size_t)w * FE) + lane);
        *(uint4*)(A + (size_t)w * AS + 128 + lane * 4) =
            make_uint4(tf32r(v.x + epsv), tf32r(v.y + epsv),
                       tf32r(v.z + epsv), tf32r(v.w + epsv));
    }
}

// ---------------------------------------------------------------------------
// Fused layer MLP, 512 threads / 16 warps (2M x 8N, warp tile 32x16).
__global__ void __launch_bounds__(NTHR, 1) k_mlp(
    const uint32_t* __restrict__ A, int l,
    const float* __restrict__ W1, const float* __restrict__ b1,
    const float* __restrict__ g1, const float* __restrict__ be1,
    const float* __restrict__ W2, const float* __restrict__ b2,
    const float* __restrict__ bng, const float* __restrict__ bnb,
    const int* __restrict__ batch,
    float* __restrict__ hout, float* __restrict__ pool) {
    extern __shared__ float sm[];
    uint32_t* smu = (uint32_t*)sm;
    int* sBt = (int*)sm + F_BT;
    int tid = threadIdx.x, wid = tid >> 5, lane = tid & 31;
    int g = lane >> 2, t = lane & 3;
    int wm = wid & 1, wn = wid >> 1;   // 2 (M) x 8 (N) warps, warp tile 32x16

    uint32_t sA;
    { void* p = (void*)(smu + F_A); sA = (uint32_t)__cvta_generic_to_shared(p); }

    if (tid < DH) {
        float a1v = __ldg(&g1[l * DH + tid]) * BN_SCALE;
        sm[F_AL1 + tid] = a1v;
        sm[F_BE1 + tid] = a1v * __ldg(&b1[l * DH + tid]) + __ldg(&be1[l * DH + tid]);
        float a2v = __ldg(&bng[l * DH + tid]) * BN_SCALE;
        sm[F_AL2 + tid] = a2v;
        sm[F_BE2 + tid] = a2v * __ldg(&b2[l * DH + tid]) + __ldg(&bnb[l * DH + tid]);
    }
    {   // weights (shift-swizzle: addr = k*128 + ((n + 8k) & 127))
        const float* Wl = W1 + (size_t)l * DC * DH;
        for (int idx = tid; idx < DC * DH; idx += NTHR) {
            int k = idx >> 7, n = idx & 127;
            smu[F_W1 + k * DH + ((n + 8 * k) & 127)] = tf32r(__ldg(&Wl[idx]));
        }
        const float* W2l = W2 + (size_t)l * DH * DH;
        for (int idx = tid; idx < DH * DH; idx += NTHR) {
            int k = idx >> 7, n = idx & 127;
            smu[F_W2 + k * DH + ((n + 8 * k) & 127)] = tf32r(__ldg(&W2l[idx]));
        }
    }

    int tile = blockIdx.x;
    if (tile < NT) {   // prefetch first A tile
        const float4* src = (const float4*)(A + (size_t)tile * BM * AS);
        for (int idx = tid; idx < BM * AS / 4; idx += NTHR)
            cp_async16(sA + idx * 16, src + idx);
        CP_COMMIT();
    }

    for (; tile < NT; tile += GRID_F) {
        int m0 = tile * BM;
        CP_WAIT0();
        __syncthreads();                 // A(t) ready; prev pooling done
        if (tid < BM)
            sBt[tid] = (m0 + tid < NN) ? __ldg(&batch[m0 + tid]) : -1;

        // ---- GEMM1: A[64x144] @ W1[144x128] ----
        float acc[2][2][4];
#pragma unroll
        for (int mi = 0; mi < 2; mi++)
#pragma unroll
            for (int nj = 0; nj < 2; nj++)
#pragma unroll
                for (int q = 0; q < 4; q++) acc[mi][nj][q] = 0.f;
        {
            const uint32_t* Ab = smu + F_A;
            const uint32_t* Bb = smu + F_W1;
#pragma unroll 6
            for (int ks = 0; ks < 18; ks++) {
                int k0 = ks * 8;
                uint32_t af[2][4], bf[2][2];
#pragma unroll
                for (int mi = 0; mi < 2; mi++) {
                    int r = wm * 32 + mi * 16;
                    af[mi][0] = Ab[(r + g) * AS + k0 + t];
                    af[mi][1] = Ab[(r + g + 8) * AS + k0 + t];
                    af[mi][2] = Ab[(r + g) * AS + k0 + 4 + t];
                    af[mi][3] = Ab[(r + g + 8) * AS + k0 + 4 + t];
                }
                int r1 = k0 + t, r2 = k0 + 4 + t;
#pragma unroll
                for (int nj = 0; nj < 2; nj++) {
                    int cg = wn * 16 + nj * 8 + g;
                    bf[nj][0] = Bb[r1 * DH + ((cg + 8 * r1) & 127)];
                    bf[nj][1] = Bb[r2 * DH + ((cg + 8 * r2) & 127)];
                }
#pragma unroll
                for (int mi = 0; mi < 2; mi++)
#pragma unroll
                    for (int nj = 0; nj < 2; nj++)
                        mma_tf32(acc[mi][nj], af[mi][0], af[mi][1], af[mi][2], af[mi][3],
                                 bf[nj][0], bf[nj][1]);
            }
        }
        // epilogue1: BN + ReLU -> h1 smem (tf32 bits)
#pragma unroll
        for (int mi = 0; mi < 2; mi++)
#pragma unroll
            for (int nj = 0; nj < 2; nj++) {
                int col = wn * 16 + nj * 8 + 2 * t;
                float al0 = sm[F_AL1 + col], al1 = sm[F_AL1 + col + 1];
                float be0 = sm[F_BE1 + col], be1v = sm[F_BE1 + col + 1];
#pragma unroll
                for (int pp = 0; pp < 2; pp++) {
                    int row = wm * 32 + mi * 16 + g + pp * 8;
                    float v0 = fmaxf(al0 * acc[mi][nj][pp * 2] + be0, 0.f);
                    float v1 = fmaxf(al1 * acc[mi][nj][pp * 2 + 1] + be1v, 0.f);
                    *(uint2*)(smu + F_H1 + row * HS + col) = make_uint2(tf32r(v0), tf32r(v1));
                }
            }
        __syncthreads();                 // h1 complete; A reads done

        // prefetch next A tile (lands during GEMM2 + epilogue + pooling)
        {
            int tn = tile + GRID_F;
            if (tn < NT) {
                const float4* src = (const float4*)(A + (size_t)tn * BM * AS);
                for (int idx = tid; idx < BM * AS / 4; idx += NTHR)
                    cp_async16(sA + idx * 16, src + idx);
            }
            CP_COMMIT();
        }

        // ---- GEMM2: h1[64x128] @ W2[128x128] ----
#pragma unroll
        for (int mi = 0; mi < 2; mi++)
#pragma unroll
            for (int nj = 0; nj < 2; nj++)
#pragma unroll
                for (int q = 0; q < 4; q++) acc[mi][nj][q] = 0.f;
        {
            const uint32_t* Ab = smu + F_H1;
            const uint32_t* Bb = smu + F_W2;
#pragma unroll 8
            for (int ks = 0; ks < 16; ks++) {
                int k0 = ks * 8;
                uint32_t af[2][4], bf[2][2];
#pragma unroll
                for (int mi = 0; mi < 2; mi++) {
                    int r = wm * 32 + mi * 16;
                    af[mi][0] = Ab[(r + g) * HS + k0 + t];
                    af[mi][1] = Ab[(r + g + 8) * HS + k0 + t];
                    af[mi][2] = Ab[(r + g) * HS + k0 + 4 + t];
                    af[mi][3] = Ab[(r + g + 8) * HS + k0 + 4 + t];
                }
                int r1 = k0 + t, r2 = k0 + 4 + t;
#pragma unroll
                for (int nj = 0; nj < 2; nj++) {
                    int cg = wn * 16 + nj * 8 + g;
                    bf[nj][0] = Bb[r1 * DH + ((cg + 8 * r1) & 127)];
                    bf[nj][1] = Bb[r2 * DH + ((cg + 8 * r2) & 127)];
                }
#pragma unroll
                for (int mi = 0; mi < 2; mi++)
#pragma unroll
                    for (int nj = 0; nj < 2; nj++)
                        mma_tf32(acc[mi][nj], af[mi][0], af[mi][1], af[mi][2], af[mi][3],
                                 bf[nj][0], bf[nj][1]);
            }
        }
        __syncthreads();                 // all warps done reading h1 region

        // epilogue2: BN + ReLU -> gmem + smem (overwrites h1 region)
#pragma unroll
        for (int mi = 0; mi < 2; mi++)
#pragma unroll
            for (int nj = 0; nj < 2; nj++) {
                int col = wn * 16 + nj * 8 + 2 * t;
                float al0 = sm[F_AL2 + col], al1 = sm[F_AL2 + col + 1];
                float be0 = sm[F_BE2 + col], be1v = sm[F_BE2 + col + 1];
#pragma unroll
                for (int pp = 0; pp < 2; pp++) {
                    int row = wm * 32 + mi * 16 + g + pp * 8;
                    int node = m0 + row;
                    float v0 = fmaxf(al0 * acc[mi][nj][pp * 2] + be0, 0.f);
                    float v1 = fmaxf(al1 * acc[mi][nj][pp * 2 + 1] + be1v, 0.f);
                    *(float2*)(sm + F_H1 + row * HS + col) = make_float2(v0, v1);
                    if (node < NN)
                        *(float2*)(hout + (size_t)node * DH + col) = make_float2(v0, v1);
                }
            }
        __syncthreads();                 // staged output complete

        // per-graph pooling: 4 parts x 128 cols, 16 rows each
        {
            int c = tid & 127, part = tid >> 7;
            int r0 = part * 16;
            float s = 0.f; int curg = sBt[r0];
#pragma unroll 4
            for (int rr = r0; rr < r0 + 16; rr++) {
                int gg = sBt[rr];
                if (gg != curg) {
                    if (curg >= 0) atomicAdd(&pool[curg * DH + c], s);
                    s = 0.f; curg = gg;
                }
                if (gg >= 0) s += sm[F_H1 + rr * HS + c];
            }
            if (curg >= 0) atomicAdd(&pool[curg * DH + c], s);
        }
    }
}

// ---------------------------------------------------------------------------
extern "C" void kernel_launch(void* const* d_in, const int* in_sizes, int n_in,
                              void* d_out, int out_size) {
    const float* x    = (const float*)d_in[0];
    const float* eatt = (const float*)d_in[1];
    const float* eps  = (const float*)d_in[2];
    const float* W1   = (const float*)d_in[3];
    const float* b1   = (const float*)d_in[4];
    const float* g1   = (const float*)d_in[5];
    const float* be1  = (const float*)d_in[6];
    const float* W2   = (const float*)d_in[7];
    const float* b2   = (const float*)d_in[8];
    const float* bng  = (const float*)d_in[9];
    const float* bnb  = (const float*)d_in[10];
    const float* Wp   = (const float*)d_in[11];
    const float* bp   = (const float*)d_in[12];
    const int* edge_dst = (const int*)d_in[14];
    const int* batch    = (const int*)d_in[15];
    float* out = (float*)d_out;

    uint32_t* p_A;
    float *p_hb0, *p_hb1, *p_er, *p_pool;
    cudaGetSymbolAddress((void**)&p_A,    g_A);
    cudaGetSymbolAddress((void**)&p_hb0,  g_hb0);
    cudaGetSymbolAddress((void**)&p_hb1,  g_hb1);
    cudaGetSymbolAddress((void**)&p_er,   g_edge_rep);
    cudaGetSymbolAddress((void**)&p_pool, g_pool);

    cudaFuncSetAttribute(k_mlp, cudaFuncAttributeMaxDynamicSharedMemorySize, SMEM_F);

    k_zero<<<(POOLN + 255) / 256, 256>>>(p_pool, POOLN);
    k_edge_rep<<<(NN * 4 + 255) / 256, 256>>>(eatt, p_er);
    k_pool_rep<<<NT, 128>>>(x, batch, p_pool);   // rep 0

    const float* hin = x;
    float* bufs[2] = {p_hb0, p_hb1};
    for (int l = 0; l < NL; l++) {
        float* hout = bufs[l & 1];
        k_gather<<<NN / 8, 256>>>(hin, edge_dst, eps, l, p_er, p_A);
        k_mlp<<<GRID_F, NTHR, SMEM_F>>>(p_A, l, W1, b1, g1, be1,
                                        W2, b2, bng, bnb, batch,
                                        hout, p_pool + (size_t)(l + 1) * NG * DH);
        hin = hout;
    }
    k_final<<<1, NG * DOUT>>>(p_pool, Wp, bp, out);
}

// round 15
// speedup vs baseline: 1.3370x; 1.3370x over previous
#include <cuda_runtime.h>
#include <cstdint>
#include <cstddef>

#define NN    50000
#define DEG   16
#define FE    16
#define DH    128
#define DC    144
#define NL    3
#define NG    64
#define DOUT  10
#define BN_SCALE 0.9999950000374997f

#define BM    64
#define NT    ((NN + BM - 1) / BM)      // 782 tiles (NT*BM = 50048)
#define NPAD  (NT * BM)                 // 50048
#define GRID_F 152                      // persistent CTAs (1/SM)
#define POOLN ((NL + 1) * NG * DH)

#define AS 148      // A row stride (floats); af banks (20g+t) conflict-free
#define HS 132      // h1 row stride; af banks (4g+t) conflict-free

// ---- fused-kernel smem (float indices) ----
#define F_AL1 0
#define F_BE1 128
#define F_AL2 256
#define F_BE2 384
#define F_BT  512                        // 64 ints
#define F_W1  640
#define F_W2  (F_W1 + DC * DH)           // 19072
#define F_A   (F_W2 + DH * DH)           // 35456
#define F_H1  (F_A + BM * AS)            // 44928
#define F_TOT (F_H1 + BM * HS)           // 53376 floats = 213504 B
#define SMEM_F (F_TOT * 4)

// ---- device scratch ----
__device__ uint32_t g_A[(size_t)NPAD * AS];   // gathered features (tf32 bits)
__device__ float g_hb0[(size_t)NN * DH];
__device__ float g_hb1[(size_t)NN * DH];
__device__ float g_edge_rep[(size_t)NN * FE];
__device__ float g_pool[POOLN];

// ---------------- helpers ----------------
__device__ __forceinline__ uint32_t tf32r(float x) {
    uint32_t r; asm("cvt.rna.tf32.f32 %0, %1;" : "=r"(r) : "f"(x)); return r;
}
__device__ __forceinline__ void mma_tf32(float* d,
                                         uint32_t a0, uint32_t a1, uint32_t a2, uint32_t a3,
                                         uint32_t b0, uint32_t b1) {
    asm volatile(
        "mma.sync.aligned.m16n8k8.row.col.f32.tf32.tf32.f32 "
        "{%0,%1,%2,%3}, {%4,%5,%6,%7}, {%8,%9}, {%0,%1,%2,%3};"
        : "+f"(d[0]), "+f"(d[1]), "+f"(d[2]), "+f"(d[3])
        : "r"(a0), "r"(a1), "r"(a2), "r"(a3), "r"(b0), "r"(b1));
}
__device__ __forceinline__ void cp_async16(uint32_t saddr, const void* gaddr) {
    asm volatile("cp.async.cg.shared.global [%0], [%1], 16;" :: "r"(saddr), "l"(gaddr));
}
#define CP_COMMIT() asm volatile("cp.async.commit_group;" ::: "memory")
#define CP_WAIT0()  asm volatile("cp.async.wait_group 0;" ::: "memory")

// ---------------- small kernels ----------------
__global__ void k_zero(float* __restrict__ p, int n) {
    int i = blockIdx.x * blockDim.x + threadIdx.x;
    if (i < n) p[i] = 0.f;
}
// edge_rep: 4 threads/node, LDG.128 per edge-feature quad.
__global__ void k_edge_rep(const float* __restrict__ ea, float* __restrict__ er) {
    int t4 = blockIdx.x * blockDim.x + threadIdx.x;
    if (t4 >= NN * 4) return;
    int i = t4 >> 2, q = t4 & 3;
    const float4* base = (const float4*)(ea + ((size_t)i * DEG) * FE) + q;
    float4 s = make_float4(1.f, 1.f, 1.f, 1.f);
#pragma unroll
    for (int k = 0; k < DEG; k++) {
        float4 v = __ldg(base + k * 4);
        s.x += v.x; s.y += v.y; s.z += v.z; s.w += v.w;
    }
    ((float4*)(er + (size_t)i * FE))[q] = s;
}
__global__ void __launch_bounds__(128) k_pool_rep(
    const float* __restrict__ h, const int* __restrict__ batch,
    float* __restrict__ pool) {
    __shared__ int sb[BM];
    int m0 = blockIdx.x * BM;
    if (threadIdx.x < BM)
        sb[threadIdx.x] = (m0 + threadIdx.x < NN) ? __ldg(&batch[m0 + threadIdx.x]) : -1;
    __syncthreads();
    int c = threadIdx.x;
    float s = 0.f; int curg = sb[0];
#pragma unroll
    for (int r0 = 0; r0 < BM; r0 += 8) {
        float v[8];
#pragma unroll
        for (int j = 0; j < 8; j++) {
            int node = m0 + r0 + j;
            v[j] = (node < NN) ? __ldg(&h[(size_t)node * DH + c]) : 0.f;
        }
#pragma unroll
        for (int j = 0; j < 8; j++) {
            int g = sb[r0 + j];
            if (g != curg) {
                if (curg >= 0) atomicAdd(&pool[curg * DH + c], s);
                s = 0.f; curg = g;
            }
            s += v[j];
        }
    }
    if (curg >= 0) atomicAdd(&pool[curg * DH + c], s);
}
__global__ void k_final(const float* __restrict__ pool, const float* __restrict__ Wp,
                        const float* __restrict__ bp, float* __restrict__ out) {
    int t = threadIdx.x;
    if (t >= NG * DOUT) return;
    int g = t / DOUT, o = t % DOUT;
    float s = 0.f;
#pragma unroll
    for (int l = 0; l < NL + 1; l++) s += __ldg(&bp[l * DOUT + o]);
#pragma unroll
    for (int l = 0; l < NL + 1; l++) {
        const float* P = pool + l * NG * DH + g * DH;
        const float* W = Wp + l * DH * DOUT;
        for (int k = 0; k < DH; k++) s += P[k] * __ldg(&W[k * DOUT + o]);
    }
    out[t] = s;
}

// ---------------------------------------------------------------------------
// Gather: warp per node, lane owns 4 cols -> coalesced LDG.128 per neighbor row.
__global__ void __launch_bounds__(256) k_gather(
    const float* __restrict__ hin, const int* __restrict__ edge_dst,
    const float* __restrict__ eps, int l,
    const float* __restrict__ er, uint32_t* __restrict__ A) {
    int w = (blockIdx.x * 256 + threadIdx.x) >> 5;
    int lane = threadIdx.x & 31;
    float epsv = __ldg(&eps[l]);
    float e1 = 1.f + epsv;

    int dv = __ldg(edge_dst + (size_t)w * DEG + (lane & 15));
    float4 own = __ldg((const float4*)(hin + (size_t)w * DH) + lane);
    float4 acc0, acc1;
    acc0.x = own.x * e1; acc0.y = own.y * e1; acc0.z = own.z * e1; acc0.w = own.w * e1;
    acc1 = make_float4(0.f, 0.f, 0.f, 0.f);
#pragma unroll
    for (int k = 0; k < DEG; k += 2) {
        int d0 = __shfl_sync(0xffffffffu, dv, k);
        int d1 = __shfl_sync(0xffffffffu, dv, k + 1);
        float4 v0 = __ldg((const float4*)(hin + (size_t)d0 * DH) + lane);
        float4 v1 = __ldg((const float4*)(hin + (size_t)d1 * DH) + lane);
        acc0.x += v0.x; acc0.y += v0.y; acc0.z += v0.z; acc0.w += v0.w;
        acc1.x += v1.x; acc1.y += v1.y; acc1.z += v1.z; acc1.w += v1.w;
    }
    float4 a;
    a.x = acc0.x + acc1.x; a.y = acc0.y + acc1.y;
    a.z = acc0.z + acc1.z; a.w = acc0.w + acc1.w;
    *(uint4*)(A + (size_t)w * AS + lane * 4) =
        make_uint4(tf32r(a.x), tf32r(a.y), tf32r(a.z), tf32r(a.w));
    if (lane < 4) {
        float4 v = __ldg((const float4*)(er + (size_t)w * FE) + lane);
        *(uint4*)(A + (size_t)w * AS + 128 + lane * 4) =
            make_uint4(tf32r(v.x + epsv), tf32r(v.y + epsv),
                       tf32r(v.z + epsv), tf32r(v.w + epsv));
    }
}

// ---------------------------------------------------------------------------
// Fused layer MLP: 256 threads, 8 warps (2M x 4N, warp tile 32x32).
__global__ void __launch_bounds__(256, 1) k_mlp(
    const uint32_t* __restrict__ A, int l,
    const float* __restrict__ W1, const float* __restrict__ b1,
    const float* __restrict__ g1, const float* __restrict__ be1,
    const float* __restrict__ W2, const float* __restrict__ b2,
    const float* __restrict__ bng, const float* __restrict__ bnb,
    const int* __restrict__ batch,
    float* __restrict__ hout, float* __restrict__ pool) {
    extern __shared__ float sm[];
    uint32_t* smu = (uint32_t*)sm;
    int* sBt = (int*)sm + F_BT;
    int tid = threadIdx.x, wid = tid >> 5, lane = tid & 31;
    int g = lane >> 2, t = lane & 3;
    int wm = wid & 1, wn = wid >> 1;   // 2 (M) x 4 (N) warps, warp tile 32x32

    uint32_t sA;
    { void* p = (void*)(smu + F_A); sA = (uint32_t)__cvta_generic_to_shared(p); }

    if (tid < DH) {
        float a1v = __ldg(&g1[l * DH + tid]) * BN_SCALE;
        sm[F_AL1 + tid] = a1v;
        sm[F_BE1 + tid] = a1v * __ldg(&b1[l * DH + tid]) + __ldg(&be1[l * DH + tid]);
        float a2v = __ldg(&bng[l * DH + tid]) * BN_SCALE;
        sm[F_AL2 + tid] = a2v;
        sm[F_BE2 + tid] = a2v * __ldg(&b2[l * DH + tid]) + __ldg(&bnb[l * DH + tid]);
    }
    {   // weights (shift-swizzle: addr = k*128 + ((n + 8k) & 127))
        const float* Wl = W1 + (size_t)l * DC * DH;
        for (int idx = tid; idx < DC * DH; idx += 256) {
            int k = idx >> 7, n = idx & 127;
            smu[F_W1 + k * DH + ((n + 8 * k) & 127)] = tf32r(__ldg(&Wl[idx]));
        }
        const float* W2l = W2 + (size_t)l * DH * DH;
        for (int idx = tid; idx < DH * DH; idx += 256) {
            int k = idx >> 7, n = idx & 127;
            smu[F_W2 + k * DH + ((n + 8 * k) & 127)] = tf32r(__ldg(&W2l[idx]));
        }
    }

    int tile = blockIdx.x;
    if (tile < NT) {   // prefetch first A tile
        const float4* src = (const float4*)(A + (size_t)tile * BM * AS);
        for (int idx = tid; idx < BM * AS / 4; idx += 256)
            cp_async16(sA + idx * 16, src + idx);
        CP_COMMIT();
    }

    for (; tile < NT; tile += GRID_F) {
        int m0 = tile * BM;
        CP_WAIT0();
        __syncthreads();                 // A(t) ready; prev pooling done
        if (tid < BM)
            sBt[tid] = (m0 + tid < NN) ? __ldg(&batch[m0 + tid]) : -1;

        // ---- GEMM1: A[64x144] @ W1[144x128] ----
        float acc[2][4][4];
#pragma unroll
        for (int mi = 0; mi < 2; mi++)
#pragma unroll
            for (int nj = 0; nj < 4; nj++)
#pragma unroll
                for (int q = 0; q < 4; q++) acc[mi][nj][q] = 0.f;
        {
            const uint32_t* Ab = smu + F_A;
            const uint32_t* Bb = smu + F_W1;
#pragma unroll 6
            for (int ks = 0; ks < 18; ks++) {
                int k0 = ks * 8;
                uint32_t af[2][4], bf[4][2];
#pragma unroll
                for (int mi = 0; mi < 2; mi++) {
                    int r = wm * 32 + mi * 16;
                    af[mi][0] = Ab[(r + g) * AS + k0 + t];
                    af[mi][1] = Ab[(r + g + 8) * AS + k0 + t];
                    af[mi][2] = Ab[(r + g) * AS + k0 + 4 + t];
                    af[mi][3] = Ab[(r + g + 8) * AS + k0 + 4 + t];
                }
                int r1 = k0 + t, r2 = k0 + 4 + t;
#pragma unroll
                for (int nj = 0; nj < 4; nj++) {
                    int cg = wn * 32 + nj * 8 + g;
                    bf[nj][0] = Bb[r1 * DH + ((cg + 8 * r1) & 127)];
                    bf[nj][1] = Bb[r2 * DH + ((cg + 8 * r2) & 127)];
                }
#pragma unroll
                for (int mi = 0; mi < 2; mi++)
#pragma unroll
                    for (int nj = 0; nj < 4; nj++)
                        mma_tf32(acc[mi][nj], af[mi][0], af[mi][1], af[mi][2], af[mi][3],
                                 bf[nj][0], bf[nj][1]);
            }
        }
        // epilogue1: BN + ReLU -> h1 smem (tf32 bits)
#pragma unroll
        for (int mi = 0; mi < 2; mi++)
#pragma unroll
            for (int nj = 0; nj < 4; nj++) {
                int col = wn * 32 + nj * 8 + 2 * t;
                float al0 = sm[F_AL1 + col], al1 = sm[F_AL1 + col + 1];
                float be0 = sm[F_BE1 + col], be1v = sm[F_BE1 + col + 1];
#pragma unroll
                for (int pp = 0; pp < 2; pp++) {
                    int row = wm * 32 + mi * 16 + g + pp * 8;
                    float v0 = fmaxf(al0 * acc[mi][nj][pp * 2] + be0, 0.f);
                    float v1 = fmaxf(al1 * acc[mi][nj][pp * 2 + 1] + be1v, 0.f);
                    *(uint2*)(smu + F_H1 + row * HS + col) = make_uint2(tf32r(v0), tf32r(v1));
                }
            }
        __syncthreads();                 // h1 complete; A reads done

        // prefetch next A tile (lands during GEMM2 + epilogue + pooling)
        {
            int tn = tile + GRID_F;
            if (tn < NT) {
                const float4* src = (const float4*)(A + (size_t)tn * BM * AS);
                for (int idx = tid; idx < BM * AS / 4; idx += 256)
                    cp_async16(sA + idx * 16, src + idx);
            }
            CP_COMMIT();
        }

        // ---- GEMM2: h1[64x128] @ W2[128x128] ----
#pragma unroll
        for (int mi = 0; mi < 2; mi++)
#pragma unroll
            for (int nj = 0; nj < 4; nj++)
#pragma unroll
                for (int q = 0; q < 4; q++) acc[mi][nj][q] = 0.f;
        {
            const uint32_t* Ab = smu + F_H1;
            const uint32_t* Bb = smu + F_W2;
#pragma unroll 8
            for (int ks = 0; ks < 16; ks++) {
                int k0 = ks * 8;
                uint32_t af[2][4], bf[4][2];
#pragma unroll
                for (int mi = 0; mi < 2; mi++) {
                    int r = wm * 32 + mi * 16;
                    af[mi][0] = Ab[(r + g) * HS + k0 + t];
                    af[mi][1] = Ab[(r + g + 8) * HS + k0 + t];
                    af[mi][2] = Ab[(r + g) * HS + k0 + 4 + t];
                    af[mi][3] = Ab[(r + g + 8) * HS + k0 + 4 + t];
                }
                int r1 = k0 + t, r2 = k0 + 4 + t;
#pragma unroll
                for (int nj = 0; nj < 4; nj++) {
                    int cg = wn * 32 + nj * 8 + g;
                    bf[nj][0] = Bb[r1 * DH + ((cg + 8 * r1) & 127)];
                    bf[nj][1] = Bb[r2 * DH + ((cg + 8 * r2) & 127)];
                }
#pragma unroll
                for (int mi = 0; mi < 2; mi++)
#pragma unroll
                    for (int nj = 0; nj < 4; nj++)
                        mma_tf32(acc[mi][nj], af[mi][0], af[mi][1], af[mi][2], af[mi][3],
                                 bf[nj][0], bf[nj][1]);
            }
        }
        __syncthreads();                 // all warps done reading h1 region

        // epilogue2: BN + ReLU -> smem only (overwrites h1 region)
#pragma unroll
        for (int mi = 0; mi < 2; mi++)
#pragma unroll
            for (int nj = 0; nj < 4; nj++) {
                int col = wn * 32 + nj * 8 + 2 * t;
                float al0 = sm[F_AL2 + col], al1 = sm[F_AL2 + col + 1];
                float be0 = sm[F_BE2 + col], be1v = sm[F_BE2 + col + 1];
#pragma unroll
                for (int pp = 0; pp < 2; pp++) {
                    int row = wm * 32 + mi * 16 + g + pp * 8;
                    float v0 = fmaxf(al0 * acc[mi][nj][pp * 2] + be0, 0.f);
                    float v1 = fmaxf(al1 * acc[mi][nj][pp * 2 + 1] + be1v, 0.f);
                    *(float2*)(sm + F_H1 + row * HS + col) = make_float2(v0, v1);
                }
            }
        __syncthreads();                 // staged output complete

        // coalesced hout write (STG.128)
        for (int idx = tid; idx < BM * 32; idx += 256) {
            int r = idx >> 5, q = idx & 31;
            if (m0 + r < NN)
                ((float4*)(hout + (size_t)(m0 + r) * DH))[q] =
                    *(float4*)(sm + F_H1 + r * HS + q * 4);
        }

        // per-graph pooling: 2 halves x 128 cols, 32 rows each
        {
            int c = tid & 127, part = tid >> 7;
            int r0 = part * 32;
            float s = 0.f; int curg = sBt[r0];
#pragma unroll 4
            for (int rr = r0; rr < r0 + 32; rr++) {
                int gg = sBt[rr];
                if (gg != curg) {
                    if (curg >= 0) atomicAdd(&pool[curg * DH + c], s);
                    s = 0.f; curg = gg;
                }
                if (gg >= 0) s += sm[F_H1 + rr * HS + c];
            }
            if (curg >= 0) atomicAdd(&pool[curg * DH + c], s);
        }
    }
}

// ---------------------------------------------------------------------------
extern "C" void kernel_launch(void* const* d_in, const int* in_sizes, int n_in,
                              void* d_out, int out_size) {
    const float* x    = (const float*)d_in[0];
    const float* eatt = (const float*)d_in[1];
    const float* eps  = (const float*)d_in[2];
    const float* W1   = (const float*)d_in[3];
    const float* b1   = (const float*)d_in[4];
    const float* g1   = (const float*)d_in[5];
    const float* be1  = (const float*)d_in[6];
    const float* W2   = (const float*)d_in[7];
    const float* b2   = (const float*)d_in[8];
    const float* bng  = (const float*)d_in[9];
    const float* bnb  = (const float*)d_in[10];
    const float* Wp   = (const float*)d_in[11];
    const float* bp   = (const float*)d_in[12];
    const int* edge_dst = (const int*)d_in[14];
    const int* batch    = (const int*)d_in[15];
    float* out = (float*)d_out;

    uint32_t* p_A;
    float *p_hb0, *p_hb1, *p_er, *p_pool;
    cudaGetSymbolAddress((void**)&p_A,    g_A);
    cudaGetSymbolAddress((void**)&p_hb0,  g_hb0);
    cudaGetSymbolAddress((void**)&p_hb1,  g_hb1);
    cudaGetSymbolAddress((void**)&p_er,   g_edge_rep);
    cudaGetSymbolAddress((void**)&p_pool, g_pool);

    cudaFuncSetAttribute(k_mlp, cudaFuncAttributeMaxDynamicSharedMemorySize, SMEM_F);

    // Launch order arranged so launch index 5 (ncu -s 5 -c 1) is k_mlp (layer 1).
    k_zero<<<(POOLN + 255) / 256, 256>>>(p_pool, POOLN);                 // 0
    k_edge_rep<<<(NN * 4 + 255) / 256, 256>>>(eatt, p_er);               // 1

    const float* hin = x;
    float* bufs[2] = {p_hb0, p_hb1};
    for (int l = 0; l < NL; l++) {
        float* hout = bufs[l & 1];
        k_gather<<<NN / 8, 256>>>(hin, edge_dst, eps, l, p_er, p_A);     // 2,4,6
        k_mlp<<<GRID_F, 256, SMEM_F>>>(p_A, l, W1, b1, g1, be1,
                                       W2, b2, bng, bnb, batch,
                                       hout, p_pool + (size_t)(l + 1) * NG * DH);  // 3,5,7
        hin = hout;
    }
    k_pool_rep<<<NT, 128>>>(x, batch, p_pool);   // rep 0 (only needs x; after loop is fine)
    k_final<<<1, NG * DOUT>>>(p_pool, Wp, bp, out);
}

// round 17
// speedup vs baseline: 1.3431x; 1.0046x over previous
#include <cuda_runtime.h>
#include <cuda_fp16.h>
#include <cstdint>
#include <cstddef>

#define NN    50000
#define DEG   16
#define FE    16
#define DH    128
#define DC    144
#define NL    3
#define NG    64
#define DOUT  10
#define BN_SCALE 0.9999950000374997f

#define BM    64
#define NT    ((NN + BM - 1) / BM)      // 782
#define NPAD  (NT * BM)
#define GRID_F 304                      // 2 CTAs/SM
#define POOLN ((NL + 1) * NG * DH)

#define A2S  76     // packed A stride (words); af banks 12g+t conflict-free
#define H2S  68     // packed h1 stride (words); banks 4g+t conflict-free
#define HWRD 64     // packed h row words
#define W1KP (DC / 2)   // 72
#define W2KP (DH / 2)   // 64

// ---- smem word offsets ----
#define F_AL1 0
#define F_BE1 128
#define F_AL2 256
#define F_BE2 384
#define F_BT  512
#define F_W1  640
#define F_W2  (F_W1 + W1KP * DH)        // 9856
#define F_A   (F_W2 + W2KP * DH)        // 18048
#define F_H1  (F_A + BM * A2S)          // 22912
#define F_TOT (F_H1 + BM * H2S)         // 27264 words = 109056 B
#define SMEM_F (F_TOT * 4)

// ---- device scratch ----
__device__ uint32_t g_A[(size_t)NPAD * A2S];     // gathered features (fp16x2)
__device__ uint32_t g_hb0[(size_t)NN * HWRD];    // h (fp16x2)
__device__ uint32_t g_hb1[(size_t)NN * HWRD];
__device__ uint32_t g_x16[(size_t)NN * HWRD];    // x converted to fp16x2
__device__ float g_edge_rep[(size_t)NN * FE];
__device__ float g_pool[POOLN];

// ---------------- helpers ----------------
__device__ __forceinline__ uint32_t packh2(float a, float b) {
    __half2 h = __floats2half2_rn(a, b);
    return *reinterpret_cast<uint32_t*>(&h);
}
__device__ __forceinline__ float2 unpackh2(uint32_t u) {
    __half2 h = *reinterpret_cast<__half2*>(&u);
    return __half22float2(h);
}
__device__ __forceinline__ void mma_f16(float* d,
                                        uint32_t a0, uint32_t a1, uint32_t a2, uint32_t a3,
                                        uint32_t b0, uint32_t b1) {
    asm volatile(
        "mma.sync.aligned.m16n8k16.row.col.f32.f16.f16.f32 "
        "{%0,%1,%2,%3}, {%4,%5,%6,%7}, {%8,%9}, {%0,%1,%2,%3};"
        : "+f"(d[0]), "+f"(d[1]), "+f"(d[2]), "+f"(d[3])
        : "r"(a0), "r"(a1), "r"(a2), "r"(a3), "r"(b0), "r"(b1));
}
__device__ __forceinline__ void cp_async16(uint32_t saddr, const void* gaddr) {
    asm volatile("cp.async.cg.shared.global [%0], [%1], 16;" :: "r"(saddr), "l"(gaddr));
}
#define CP_COMMIT() asm volatile("cp.async.commit_group;" ::: "memory")
#define CP_WAIT0()  asm volatile("cp.async.wait_group 0;" ::: "memory")

// ---------------- small kernels ----------------
__global__ void k_zero(float* __restrict__ p, int n) {
    int i = blockIdx.x * blockDim.x + threadIdx.x;
    if (i < n) p[i] = 0.f;
}
__global__ void k_edge_rep(const float* __restrict__ ea, float* __restrict__ er) {
    int t4 = blockIdx.x * blockDim.x + threadIdx.x;
    if (t4 >= NN * 4) return;
    int i = t4 >> 2, q = t4 & 3;
    const float4* base = (const float4*)(ea + ((size_t)i * DEG) * FE) + q;
    float4 s = make_float4(1.f, 1.f, 1.f, 1.f);
#pragma unroll
    for (int k = 0; k < DEG; k++) {
        float4 v = __ldg(base + k * 4);
        s.x += v.x; s.y += v.y; s.z += v.z; s.w += v.w;
    }
    ((float4*)(er + (size_t)i * FE))[q] = s;
}
// x (f32) -> packed fp16x2
__global__ void k_xcvt(const float* __restrict__ x, uint32_t* __restrict__ xo) {
    int idx = blockIdx.x * blockDim.x + threadIdx.x;
    if (idx >= NN * HWRD) return;
    int row = idx >> 6, wc = idx & 63;
    float2 v = __ldg((const float2*)(x + (size_t)row * DH) + wc);
    xo[idx] = packh2(v.x, v.y);
}
__global__ void __launch_bounds__(128) k_pool_rep(
    const float* __restrict__ h, const int* __restrict__ batch,
    float* __restrict__ pool) {
    __shared__ int sb[BM];
    int m0 = blockIdx.x * BM;
    if (threadIdx.x < BM)
        sb[threadIdx.x] = (m0 + threadIdx.x < NN) ? __ldg(&batch[m0 + threadIdx.x]) : -1;
    __syncthreads();
    int c = threadIdx.x;
    float s = 0.f; int curg = sb[0];
#pragma unroll
    for (int r0 = 0; r0 < BM; r0 += 8) {
        float v[8];
#pragma unroll
        for (int j = 0; j < 8; j++) {
            int node = m0 + r0 + j;
            v[j] = (node < NN) ? __ldg(&h[(size_t)node * DH + c]) : 0.f;
        }
#pragma unroll
        for (int j = 0; j < 8; j++) {
            int g = sb[r0 + j];
            if (g != curg) {
                if (curg >= 0) atomicAdd(&pool[curg * DH + c], s);
                s = 0.f; curg = g;
            }
            s += v[j];
        }
    }
    if (curg >= 0) atomicAdd(&pool[curg * DH + c], s);
}
__global__ void k_final(const float* __restrict__ pool, const float* __restrict__ Wp,
                        const float* __restrict__ bp, float* __restrict__ out) {
    int t = threadIdx.x;
    if (t >= NG * DOUT) return;
    int g = t / DOUT, o = t % DOUT;
    float s = 0.f;
#pragma unroll
    for (int l = 0; l < NL + 1; l++) s += __ldg(&bp[l * DOUT + o]);
#pragma unroll
    for (int l = 0; l < NL + 1; l++) {
        const float* P = pool + l * NG * DH + g * DH;
        const float* W = Wp + l * DH * DOUT;
        for (int k = 0; k < DH; k++) s += P[k] * __ldg(&W[k * DOUT + o]);
    }
    out[t] = s;
}

// ---------------------------------------------------------------------------
// Gather on packed fp16 h: warp per node, lane owns 4 cols (2 packed words).
__global__ void __launch_bounds__(256) k_gather(
    const uint32_t* __restrict__ hin, const int* __restrict__ edge_dst,
    const float* __restrict__ eps, int l,
    const float* __restrict__ er, uint32_t* __restrict__ A) {
    int w = (blockIdx.x * 256 + threadIdx.x) >> 5;
    int lane = threadIdx.x & 31;
    float epsv = __ldg(&eps[l]);
    float e1 = 1.f + epsv;

    int dv = __ldg(edge_dst + (size_t)w * DEG + (lane & 15));
    uint2 ow = __ldg((const uint2*)(hin + (size_t)w * HWRD) + lane);
    float2 o0 = unpackh2(ow.x), o1 = unpackh2(ow.y);
    float4 acc0, acc1;
    acc0.x = o0.x * e1; acc0.y = o0.y * e1; acc0.z = o1.x * e1; acc0.w = o1.y * e1;
    acc1 = make_float4(0.f, 0.f, 0.f, 0.f);
#pragma unroll
    for (int k = 0; k < DEG; k += 2) {
        int d0 = __shfl_sync(0xffffffffu, dv, k);
        int d1 = __shfl_sync(0xffffffffu, dv, k + 1);
        uint2 v0 = __ldg((const uint2*)(hin + (size_t)d0 * HWRD) + lane);
        uint2 v1 = __ldg((const uint2*)(hin + (size_t)d1 * HWRD) + lane);
        float2 a = unpackh2(v0.x), b = unpackh2(v0.y);
        acc0.x += a.x; acc0.y += a.y; acc0.z += b.x; acc0.w += b.y;
        a = unpackh2(v1.x); b = unpackh2(v1.y);
        acc1.x += a.x; acc1.y += a.y; acc1.z += b.x; acc1.w += b.y;
    }
    float4 a;
    a.x = acc0.x + acc1.x; a.y = acc0.y + acc1.y;
    a.z = acc0.z + acc1.z; a.w = acc0.w + acc1.w;
    *(uint2*)(A + (size_t)w * A2S + 2 * lane) =
        make_uint2(packh2(a.x, a.y), packh2(a.z, a.w));
    if (lane < 4) {
        float4 v = __ldg((const float4*)(er + (size_t)w * FE) + lane);
        *(uint2*)(A + (size_t)w * A2S + 64 + 2 * lane) =
            make_uint2(packh2(v.x + epsv, v.y + epsv), packh2(v.z + epsv, v.w + epsv));
    }
}

// ---------------------------------------------------------------------------
// Fused layer MLP (fp16 MMA): 256 threads, 8 warps (2M x 4N, warp tile 32x32).
__global__ void __launch_bounds__(256, 2) k_mlp(
    const uint32_t* __restrict__ A, int l,
    const float* __restrict__ W1, const float* __restrict__ b1,
    const float* __restrict__ g1, const float* __restrict__ be1,
    const float* __restrict__ W2, const float* __restrict__ b2,
    const float* __restrict__ bng, const float* __restrict__ bnb,
    const int* __restrict__ batch,
    uint32_t* __restrict__ hout, float* __restrict__ pool) {
    extern __shared__ float sm[];
    uint32_t* smu = (uint32_t*)sm;
    int* sBt = (int*)sm + F_BT;
    int tid = threadIdx.x, wid = tid >> 5, lane = tid & 31;
    int g = lane >> 2, t = lane & 3;
    int wm = wid & 1, wn = wid >> 1;   // 2 (M) x 4 (N) warps, warp tile 32x32

    uint32_t sA;
    { void* p = (void*)(smu + F_A); sA = (uint32_t)__cvta_generic_to_shared(p); }

    if (tid < DH) {
        float a1v = __ldg(&g1[l * DH + tid]) * BN_SCALE;
        sm[F_AL1 + tid] = a1v;
        sm[F_BE1 + tid] = a1v * __ldg(&b1[l * DH + tid]) + __ldg(&be1[l * DH + tid]);
        float a2v = __ldg(&bng[l * DH + tid]) * BN_SCALE;
        sm[F_AL2 + tid] = a2v;
        sm[F_BE2 + tid] = a2v * __ldg(&b2[l * DH + tid]) + __ldg(&bnb[l * DH + tid]);
    }
    {   // weights -> packed fp16x2 (pair along k), shift-swizzle ((n + 8kp) & 127)
        const float* W1l = W1 + (size_t)l * DC * DH;
        for (int idx = tid; idx < W1KP * DH; idx += 256) {
            int kp = idx >> 7, n = idx & 127;
            float a = __ldg(&W1l[(2 * kp) * DH + n]);
            float b = __ldg(&W1l[(2 * kp + 1) * DH + n]);
            smu[F_W1 + kp * DH + ((n + 8 * kp) & 127)] = packh2(a, b);
        }
        const float* W2l = W2 + (size_t)l * DH * DH;
        for (int idx = tid; idx < W2KP * DH; idx += 256) {
            int kp = idx >> 7, n = idx & 127;
            float a = __ldg(&W2l[(2 * kp) * DH + n]);
            float b = __ldg(&W2l[(2 * kp + 1) * DH + n]);
            smu[F_W2 + kp * DH + ((n + 8 * kp) & 127)] = packh2(a, b);
        }
    }

    int tile = blockIdx.x;
    if (tile < NT) {   // prefetch first A tile
        const float4* src = (const float4*)(A + (size_t)tile * BM * A2S);
        for (int idx = tid; idx < BM * A2S / 4; idx += 256)
            cp_async16(sA + idx * 16, src + idx);
        CP_COMMIT();
    }

    for (; tile < NT; tile += GRID_F) {
        int m0 = tile * BM;
        CP_WAIT0();
        __syncthreads();                 // A(t) ready; prev pooling done
        if (tid < BM)
            sBt[tid] = (m0 + tid < NN) ? __ldg(&batch[m0 + tid]) : -1;

        // ---- GEMM1: A[64x144] @ W1[144x128], 9 k16-steps ----
        float acc[2][4][4];
#pragma unroll
        for (int mi = 0; mi < 2; mi++)
#pragma unroll
            for (int nj = 0; nj < 4; nj++)
#pragma unroll
                for (int q = 0; q < 4; q++) acc[mi][nj][q] = 0.f;
        {
            const uint32_t* Ab = smu + F_A;
            const uint32_t* Bb = smu + F_W1;
#pragma unroll 3
            for (int ks = 0; ks < 9; ks++) {
                int kp0 = ks * 8;
                uint32_t af[2][4], bf[4][2];
#pragma unroll
                for (int mi = 0; mi < 2; mi++) {
                    int r = wm * 32 + mi * 16;
                    af[mi][0] = Ab[(r + g) * A2S + kp0 + t];
                    af[mi][1] = Ab[(r + g + 8) * A2S + kp0 + t];
                    af[mi][2] = Ab[(r + g) * A2S + kp0 + 4 + t];
                    af[mi][3] = Ab[(r + g + 8) * A2S + kp0 + 4 + t];
                }
                int k1 = kp0 + t, k2 = kp0 + 4 + t;
#pragma unroll
                for (int nj = 0; nj < 4; nj++) {
                    int cg = wn * 32 + nj * 8 + g;
                    bf[nj][0] = Bb[k1 * DH + ((cg + 8 * k1) & 127)];
                    bf[nj][1] = Bb[k2 * DH + ((cg + 8 * k2) & 127)];
                }
#pragma unroll
                for (int mi = 0; mi < 2; mi++)
#pragma unroll
                    for (int nj = 0; nj < 4; nj++)
                        mma_f16(acc[mi][nj], af[mi][0], af[mi][1], af[mi][2], af[mi][3],
                                bf[nj][0], bf[nj][1]);
            }
        }
        // epilogue1: BN + ReLU -> h1 smem (fp16x2)
#pragma unroll
        for (int mi = 0; mi < 2; mi++)
#pragma unroll
            for (int nj = 0; nj < 4; nj++) {
                int col = wn * 32 + nj * 8 + 2 * t;
                float al0 = sm[F_AL1 + col], al1 = sm[F_AL1 + col + 1];
                float be0 = sm[F_BE1 + col], be1v = sm[F_BE1 + col + 1];
                int wc = wn * 16 + nj * 4 + t;   // packed word column
#pragma unroll
                for (int pp = 0; pp < 2; pp++) {
                    int row = wm * 32 + mi * 16 + g + pp * 8;
                    float v0 = fmaxf(al0 * acc[mi][nj][pp * 2] + be0, 0.f);
                    float v1 = fmaxf(al1 * acc[mi][nj][pp * 2 + 1] + be1v, 0.f);
                    smu[F_H1 + row * H2S + wc] = packh2(v0, v1);
                }
            }
        __syncthreads();                 // h1 complete; A reads done

        // prefetch next A tile
        {
            int tn = tile + GRID_F;
            if (tn < NT) {
                const float4* src = (const float4*)(A + (size_t)tn * BM * A2S);
                for (int idx = tid; idx < BM * A2S / 4; idx += 256)
                    cp_async16(sA + idx * 16, src + idx);
            }
            CP_COMMIT();
        }

        // ---- GEMM2: h1[64x128] @ W2[128x128], 8 k16-steps ----
#pragma unroll
        for (int mi = 0; mi < 2; mi++)
#pragma unroll
            for (int nj = 0; nj < 4; nj++)
#pragma unroll
                for (int q = 0; q < 4; q++) acc[mi][nj][q] = 0.f;
        {
            const uint32_t* Ab = smu + F_H1;
            const uint32_t* Bb = smu + F_W2;
#pragma unroll 4
            for (int ks = 0; ks < 8; ks++) {
                int kp0 = ks * 8;
                uint32_t af[2][4], bf[4][2];
#pragma unroll
                for (int mi = 0; mi < 2; mi++) {
                    int r = wm * 32 + mi * 16;
                    af[mi][0] = Ab[(r + g) * H2S + kp0 + t];
                    af[mi][1] = Ab[(r + g + 8) * H2S + kp0 + t];
                    af[mi][2] = Ab[(r + g) * H2S + kp0 + 4 + t];
                    af[mi][3] = Ab[(r + g + 8) * H2S + kp0 + 4 + t];
                }
                int k1 = kp0 + t, k2 = kp0 + 4 + t;
#pragma unroll
                for (int nj = 0; nj < 4; nj++) {
                    int cg = wn * 32 + nj * 8 + g;
                    bf[nj][0] = Bb[k1 * DH + ((cg + 8 * k1) & 127)];
                    bf[nj][1] = Bb[k2 * DH + ((cg + 8 * k2) & 127)];
                }
#pragma unroll
                for (int mi = 0; mi < 2; mi++)
#pragma unroll
                    for (int nj = 0; nj < 4; nj++)
                        mma_f16(acc[mi][nj], af[mi][0], af[mi][1], af[mi][2], af[mi][3],
                                bf[nj][0], bf[nj][1]);
            }
        }
        __syncthreads();                 // all warps done reading h1 region

        // epilogue2: BN + ReLU -> smem packed fp16 (overwrites h1 region)
#pragma unroll
        for (int mi = 0; mi < 2; mi++)
#pragma unroll
            for (int nj = 0; nj < 4; nj++) {
                int col = wn * 32 + nj * 8 + 2 * t;
                float al0 = sm[F_AL2 + col], al1 = sm[F_AL2 + col + 1];
                float be0 = sm[F_BE2 + col], be1v = sm[F_BE2 + col + 1];
                int wc = wn * 16 + nj * 4 + t;
#pragma unroll
                for (int pp = 0; pp < 2; pp++) {
                    int row = wm * 32 + mi * 16 + g + pp * 8;
                    float v0 = fmaxf(al0 * acc[mi][nj][pp * 2] + be0, 0.f);
                    float v1 = fmaxf(al1 * acc[mi][nj][pp * 2 + 1] + be1v, 0.f);
                    smu[F_H1 + row * H2S + wc] = packh2(v0, v1);
                }
            }
        __syncthreads();                 // staged output complete

        // coalesced hout write (uint4 = 8 cols)
        for (int idx = tid; idx < BM * 16; idx += 256) {
            int r = idx >> 4, q = idx & 15;
            if (m0 + r < NN)
                ((uint4*)(hout + (size_t)(m0 + r) * HWRD))[q] =
                    *(uint4*)(smu + F_H1 + r * H2S + q * 4);
        }

        // per-graph pooling: 4 parts x 64 word-cols, 16 rows each
        {
            int c = tid & 63, part = tid >> 6;
            int r0 = part * 16;
            float s0 = 0.f, s1 = 0.f; int curg = sBt[r0];
#pragma unroll 4
            for (int rr = r0; rr < r0 + 16; rr++) {
                int gg = sBt[rr];
                if (gg != curg) {
                    if (curg >= 0) {
                        atomicAdd(&pool[curg * DH + 2 * c], s0);
                        atomicAdd(&pool[curg * DH + 2 * c + 1], s1);
                    }
                    s0 = s1 = 0.f; curg = gg;
                }
                if (gg >= 0) {
                    float2 v = unpackh2(smu[F_H1 + rr * H2S + c]);
                    s0 += v.x; s1 += v.y;
                }
            }
            if (curg >= 0) {
                atomicAdd(&pool[curg * DH + 2 * c], s0);
                atomicAdd(&pool[curg * DH + 2 * c + 1], s1);
            }
        }
    }
}

// ---------------------------------------------------------------------------
extern "C" void kernel_launch(void* const* d_in, const int* in_sizes, int n_in,
                              void* d_out, int out_size) {
    const float* x    = (const float*)d_in[0];
    const float* eatt = (const float*)d_in[1];
    const float* eps  = (const float*)d_in[2];
    const float* W1   = (const float*)d_in[3];
    const float* b1   = (const float*)d_in[4];
    const float* g1   = (const float*)d_in[5];
    const float* be1  = (const float*)d_in[6];
    const float* W2   = (const float*)d_in[7];
    const float* b2   = (const float*)d_in[8];
    const float* bng  = (const float*)d_in[9];
    const float* bnb  = (const float*)d_in[10];
    const float* Wp   = (const float*)d_in[11];
    const float* bp   = (const float*)d_in[12];
    const int* edge_dst = (const int*)d_in[14];
    const int* batch    = (const int*)d_in[15];
    float* out = (float*)d_out;

    uint32_t *p_A, *p_hb0, *p_hb1, *p_x16;
    float *p_er, *p_pool;
    cudaGetSymbolAddress((void**)&p_A,    g_A);
    cudaGetSymbolAddress((void**)&p_hb0,  g_hb0);
    cudaGetSymbolAddress((void**)&p_hb1,  g_hb1);
    cudaGetSymbolAddress((void**)&p_x16,  g_x16);
    cudaGetSymbolAddress((void**)&p_er,   g_edge_rep);
    cudaGetSymbolAddress((void**)&p_pool, g_pool);

    cudaFuncSetAttribute(k_mlp, cudaFuncAttributeMaxDynamicSharedMemorySize, SMEM_F);

    // Launch order: index 5 (ncu -s 5 -c 1) = k_mlp layer 0.
    k_zero<<<(POOLN + 255) / 256, 256>>>(p_pool, POOLN);                 // 0
    k_edge_rep<<<(NN * 4 + 255) / 256, 256>>>(eatt, p_er);               // 1
    k_pool_rep<<<NT, 128>>>(x, batch, p_pool);                           // 2 (rep 0, f32 x)
    k_xcvt<<<(NN * HWRD + 255) / 256, 256>>>(x, p_x16);                  // 3

    const uint32_t* hin = p_x16;
    uint32_t* bufs[2] = {p_hb0, p_hb1};
    for (int l = 0; l < NL; l++) {
        uint32_t* hout = bufs[l & 1];
        k_gather<<<NN / 8, 256>>>(hin, edge_dst, eps, l, p_er, p_A);     // 4,6,8
        k_mlp<<<GRID_F, 256, SMEM_F>>>(p_A, l, W1, b1, g1, be1,
                                       W2, b2, bng, bnb, batch,
                                       hout, p_pool + (size_t)(l + 1) * NG * DH);  // 5,7,9
        hin = hout;
    }
    k_final<<<1, NG * DOUT>>>(p_pool, Wp, bp, out);
}